// round 9
// baseline (speedup 1.0000x reference)
#include <cuda_runtime.h>
#include <cuda_bf16.h>
#include <cstdint>

#define NN 50000
#define NE 800000
#define D  64
#define DK 128
#define CAP 96
#define HT_STRIDE 132

// Statically zero-initialized; gather_kernel resets counters after reading,
// so every graph replay starts from zeroed counters.
__device__ int   g_deg_i[NN];
__device__ int   g_slot[(size_t)NN * CAP];
__device__ float g_agg[NN * D];          // pre-divided neighbor means

// ---------------------------------------------------------------------------
// Kernel 1: bucket fill. 4 edges per thread via int4 loads.
// ---------------------------------------------------------------------------
__global__ __launch_bounds__(256) void fill_kernel(const int* __restrict__ src,
                                                   const int* __restrict__ dst) {
    int q = blockIdx.x * blockDim.x + threadIdx.x;
    if (q >= NE / 4) return;
    int4 s4 = ((const int4*)src)[q];
    int4 d4 = ((const int4*)dst)[q];
    int pos;
    pos = atomicAdd(&g_deg_i[d4.x], 1); if (pos < CAP) g_slot[(size_t)d4.x * CAP + pos] = s4.x;
    pos = atomicAdd(&g_deg_i[d4.y], 1); if (pos < CAP) g_slot[(size_t)d4.y * CAP + pos] = s4.y;
    pos = atomicAdd(&g_deg_i[d4.z], 1); if (pos < CAP) g_slot[(size_t)d4.z * CAP + pos] = s4.z;
    pos = atomicAdd(&g_deg_i[d4.w], 1); if (pos < CAP) g_slot[(size_t)d4.w * CAP + pos] = s4.w;
}

// ---------------------------------------------------------------------------
// Kernel 2: gather. Warp per node, NO shared memory -> high occupancy for
// latency hiding. Proven 4-wide float2 loop. Writes pre-divided mean.
// ---------------------------------------------------------------------------
__global__ __launch_bounds__(256) void gather_kernel(const float* __restrict__ h) {
    int warp = (blockIdx.x * 256 + threadIdx.x) >> 5;
    int lane = threadIdx.x & 31;
    if (warp >= NN) return;
    int n = warp;

    const float2* h2 = (const float2*)h;   // row stride = 32 float2

    int dg = g_deg_i[n];
    if (lane == 0) g_deg_i[n] = 0;   // self-reset for next replay
    int cnt = dg < CAP ? dg : CAP;
    const int* sl = g_slot + (size_t)n * CAP;

    float2 a = make_float2(0.f, 0.f);
    float2 c = make_float2(0.f, 0.f);
    int k = 0;
    for (; k + 4 <= cnt; k += 4) {
        int s0 = sl[k], s1 = sl[k + 1], s2 = sl[k + 2], s3 = sl[k + 3];
        float2 v0 = h2[(size_t)s0 * 32 + lane];
        float2 v1 = h2[(size_t)s1 * 32 + lane];
        float2 v2 = h2[(size_t)s2 * 32 + lane];
        float2 v3 = h2[(size_t)s3 * 32 + lane];
        a.x += v0.x; a.y += v0.y;
        c.x += v1.x; c.y += v1.y;
        a.x += v2.x; a.y += v2.y;
        c.x += v3.x; c.y += v3.y;
    }
    for (; k < cnt; k++) {
        float2 v0 = h2[(size_t)sl[k] * 32 + lane];
        a.x += v0.x; a.y += v0.y;
    }

    float inv = 1.0f / fmaxf((float)dg, 1.0f);
    float2 mn = make_float2((a.x + c.x) * inv, (a.y + c.y) * inv);
    ((float2*)g_agg)[(size_t)n * 32 + lane] = mn;
}

// ---------------------------------------------------------------------------
// Kernel 3: GEMM. 64 nodes x 64 outputs per block, 4x4 micro-tile.
// ---------------------------------------------------------------------------
__global__ __launch_bounds__(256) void gemm_kernel(const float* __restrict__ h,
                                                   const float* __restrict__ W,
                                                   const float* __restrict__ b,
                                                   float* __restrict__ out) {
    __shared__ float Ws[DK * D];          // 32 KB
    __shared__ float ht[64][HT_STRIDE];   // ~33.8 KB

    int t = threadIdx.x;
    int base = blockIdx.x * 64;

    // Stage W
    {
        const float4* Wv = (const float4*)W;
        float4* Wsv = (float4*)Ws;
        #pragma unroll
        for (int i = 0; i < 8; i++) Wsv[t + i * 256] = Wv[t + i * 256];
    }

    // Stage ht: h part (cols 0..63) and agg part (cols 64..127).
    #pragma unroll
    for (int i = 0; i < 4; i++) {
        int s = t + i * 256;          // 0..1023
        int m = s >> 4;               // node within tile
        int q = s & 15;               // float4 within 64-float row
        int node = base + m;
        int nc = node < NN ? node : NN - 1;
        float4 hv = *(const float4*)(h + (size_t)nc * D + q * 4);
        float4 av = *(const float4*)(g_agg + (size_t)nc * D + q * 4);
        *(float4*)&ht[m][q * 4]      = hv;
        *(float4*)&ht[m][64 + q * 4] = av;
    }
    __syncthreads();

    int tx = t & 15;
    int ty = t >> 4;
    int j0 = tx * 4;
    int m0 = ty * 4;

    float4 bv = *(const float4*)(b + j0);
    float acc[4][4];
    #pragma unroll
    for (int i = 0; i < 4; i++) {
        acc[i][0] = bv.x; acc[i][1] = bv.y; acc[i][2] = bv.z; acc[i][3] = bv.w;
    }

    #pragma unroll 4
    for (int k = 0; k < DK; k++) {
        float4 wv = *(const float4*)&Ws[k * D + j0];
        float a0 = ht[m0 + 0][k];
        float a1 = ht[m0 + 1][k];
        float a2 = ht[m0 + 2][k];
        float a3 = ht[m0 + 3][k];
        acc[0][0] = fmaf(a0, wv.x, acc[0][0]);
        acc[0][1] = fmaf(a0, wv.y, acc[0][1]);
        acc[0][2] = fmaf(a0, wv.z, acc[0][2]);
        acc[0][3] = fmaf(a0, wv.w, acc[0][3]);
        acc[1][0] = fmaf(a1, wv.x, acc[1][0]);
        acc[1][1] = fmaf(a1, wv.y, acc[1][1]);
        acc[1][2] = fmaf(a1, wv.z, acc[1][2]);
        acc[1][3] = fmaf(a1, wv.w, acc[1][3]);
        acc[2][0] = fmaf(a2, wv.x, acc[2][0]);
        acc[2][1] = fmaf(a2, wv.y, acc[2][1]);
        acc[2][2] = fmaf(a2, wv.z, acc[2][2]);
        acc[2][3] = fmaf(a2, wv.w, acc[2][3]);
        acc[3][0] = fmaf(a3, wv.x, acc[3][0]);
        acc[3][1] = fmaf(a3, wv.y, acc[3][1]);
        acc[3][2] = fmaf(a3, wv.z, acc[3][2]);
        acc[3][3] = fmaf(a3, wv.w, acc[3][3]);
    }

    #pragma unroll
    for (int i = 0; i < 4; i++) {
        int node = base + m0 + i;
        if (node < NN) {
            float4 o = make_float4(acc[i][0], acc[i][1], acc[i][2], acc[i][3]);
            *(float4*)(out + (size_t)node * D + j0) = o;
        }
    }
}

// ---------------------------------------------------------------------------
// Launch
// ---------------------------------------------------------------------------
extern "C" void kernel_launch(void* const* d_in, const int* in_sizes, int n_in,
                              void* d_out, int out_size) {
    const float* h   = (const float*)d_in[0];
    const int*   src = (const int*)d_in[1];
    const int*   dst = (const int*)d_in[2];
    const float* W   = (const float*)d_in[3];
    const float* b   = (const float*)d_in[4];
    float* out = (float*)d_out;

    fill_kernel<<<(NE / 4 + 255) / 256, 256>>>(src, dst);
    gather_kernel<<<(NN * 32 + 255) / 256, 256>>>(h);
    gemm_kernel<<<(NN + 63) / 64, 256>>>(h, W, b, out);
}

// round 10
// speedup vs baseline: 1.7498x; 1.7498x over previous
#include <cuda_runtime.h>
#include <cuda_bf16.h>
#include <cstdint>

#define NN 50000
#define NE 800000
#define D  64
#define DK 128
#define CAP 96
#define HT_STRIDE 132

// Statically zero-initialized; fused_kernel resets counters (post-gather),
// so every graph replay starts from zeroed counters.
__device__ int g_deg_i[NN];
__device__ int g_slot[(size_t)NN * CAP];

// ---------------------------------------------------------------------------
// Kernel 1: bucket fill. 4 edges per thread via int4 loads.
// ---------------------------------------------------------------------------
__global__ __launch_bounds__(256) void fill_kernel(const int* __restrict__ src,
                                                   const int* __restrict__ dst) {
    int q = blockIdx.x * blockDim.x + threadIdx.x;
    if (q >= NE / 4) return;
    int4 s4 = ((const int4*)src)[q];
    int4 d4 = ((const int4*)dst)[q];
    int pos;
    pos = atomicAdd(&g_deg_i[d4.x], 1); if (pos < CAP) g_slot[(size_t)d4.x * CAP + pos] = s4.x;
    pos = atomicAdd(&g_deg_i[d4.y], 1); if (pos < CAP) g_slot[(size_t)d4.y * CAP + pos] = s4.y;
    pos = atomicAdd(&g_deg_i[d4.z], 1); if (pos < CAP) g_slot[(size_t)d4.z * CAP + pos] = s4.z;
    pos = atomicAdd(&g_deg_i[d4.w], 1); if (pos < CAP) g_slot[(size_t)d4.w * CAP + pos] = s4.w;
}

// ---------------------------------------------------------------------------
// Kernel 2: fused gather + GEMM.
// Gather: identical to the proven R7 loop. GEMM: k-split into two halves so
// the W stage buffer is 16KB -> 49KB smem total -> 4 blocks/SM (was 3).
// ---------------------------------------------------------------------------
__global__ __launch_bounds__(256, 4) void fused_kernel(const float* __restrict__ h,
                                                       const float* __restrict__ W,
                                                       const float* __restrict__ b,
                                                       float* __restrict__ out) {
    __shared__ float Ws[64 * D];          // 16 KB (one k-half of W)
    __shared__ float ht[64][HT_STRIDE];   // ~33.8 KB

    int t = threadIdx.x;
    int base = blockIdx.x * 64;
    int warp = t >> 5;
    int lane = t & 31;

    const float2* h2 = (const float2*)h;   // row stride = 32 float2

    // Phase A: gather. Warp w handles nodes base + w*8 .. +7. (R7-proven)
    #pragma unroll 1
    for (int i = 0; i < 8; i++) {
        int m = warp * 8 + i;
        int node = base + m;
        if (node >= NN) break;

        // self features (features 2*lane, 2*lane+1)
        float2 sv = h2[(size_t)node * 32 + lane];
        *(float2*)&ht[m][2 * lane] = sv;

        int dg  = g_deg_i[node];
        int cnt = dg < CAP ? dg : CAP;
        const int* sl = g_slot + (size_t)node * CAP;

        float2 a = make_float2(0.f, 0.f);
        float2 c = make_float2(0.f, 0.f);
        int k = 0;
        for (; k + 4 <= cnt; k += 4) {
            int s0 = sl[k], s1 = sl[k + 1], s2 = sl[k + 2], s3 = sl[k + 3];
            float2 v0 = h2[(size_t)s0 * 32 + lane];
            float2 v1 = h2[(size_t)s1 * 32 + lane];
            float2 v2 = h2[(size_t)s2 * 32 + lane];
            float2 v3 = h2[(size_t)s3 * 32 + lane];
            a.x += v0.x; a.y += v0.y;
            c.x += v1.x; c.y += v1.y;
            a.x += v2.x; a.y += v2.y;
            c.x += v3.x; c.y += v3.y;
        }
        for (; k < cnt; k++) {
            float2 v0 = h2[(size_t)sl[k] * 32 + lane];
            a.x += v0.x; a.y += v0.y;
        }

        float inv = 1.0f / fmaxf((float)dg, 1.0f);
        float2 mn = make_float2((a.x + c.x) * inv, (a.y + c.y) * inv);
        *(float2*)&ht[m][64 + 2 * lane] = mn;
    }
    __syncthreads();

    // Reset counters for the next graph replay.
    if (t < 64) {
        int node = base + t;
        if (node < NN) g_deg_i[node] = 0;
    }

    // Phase B: GEMM in two k-halves. thread (tx,ty): 4 nodes x 4 outputs.
    int tx = t & 15;
    int ty = t >> 4;
    int j0 = tx * 4;
    int m0 = ty * 4;

    float4 bv = *(const float4*)(b + j0);
    float acc[4][4];
    #pragma unroll
    for (int i = 0; i < 4; i++) {
        acc[i][0] = bv.x; acc[i][1] = bv.y; acc[i][2] = bv.z; acc[i][3] = bv.w;
    }

    #pragma unroll 1
    for (int half = 0; half < 2; half++) {
        // Stage 64 rows of W: 4096 floats = 1024 float4 by 256 threads
        {
            const float4* Wv = (const float4*)(W + half * 64 * D);
            float4* Wsv = (float4*)Ws;
            #pragma unroll
            for (int i = 0; i < 4; i++) Wsv[t + i * 256] = Wv[t + i * 256];
        }
        __syncthreads();

        int kbase = half * 64;
        #pragma unroll 4
        for (int k = 0; k < 64; k++) {
            float4 wv = *(const float4*)&Ws[k * D + j0];
            float a0 = ht[m0 + 0][kbase + k];
            float a1 = ht[m0 + 1][kbase + k];
            float a2 = ht[m0 + 2][kbase + k];
            float a3 = ht[m0 + 3][kbase + k];
            acc[0][0] = fmaf(a0, wv.x, acc[0][0]);
            acc[0][1] = fmaf(a0, wv.y, acc[0][1]);
            acc[0][2] = fmaf(a0, wv.z, acc[0][2]);
            acc[0][3] = fmaf(a0, wv.w, acc[0][3]);
            acc[1][0] = fmaf(a1, wv.x, acc[1][0]);
            acc[1][1] = fmaf(a1, wv.y, acc[1][1]);
            acc[1][2] = fmaf(a1, wv.z, acc[1][2]);
            acc[1][3] = fmaf(a1, wv.w, acc[1][3]);
            acc[2][0] = fmaf(a2, wv.x, acc[2][0]);
            acc[2][1] = fmaf(a2, wv.y, acc[2][1]);
            acc[2][2] = fmaf(a2, wv.z, acc[2][2]);
            acc[2][3] = fmaf(a2, wv.w, acc[2][3]);
            acc[3][0] = fmaf(a3, wv.x, acc[3][0]);
            acc[3][1] = fmaf(a3, wv.y, acc[3][1]);
            acc[3][2] = fmaf(a3, wv.z, acc[3][2]);
            acc[3][3] = fmaf(a3, wv.w, acc[3][3]);
        }
        __syncthreads();   // before next half overwrites Ws
    }

    #pragma unroll
    for (int i = 0; i < 4; i++) {
        int node = base + m0 + i;
        if (node < NN) {
            float4 o = make_float4(acc[i][0], acc[i][1], acc[i][2], acc[i][3]);
            *(float4*)(out + (size_t)node * D + j0) = o;
        }
    }
}

// ---------------------------------------------------------------------------
// Launch
// ---------------------------------------------------------------------------
extern "C" void kernel_launch(void* const* d_in, const int* in_sizes, int n_in,
                              void* d_out, int out_size) {
    const float* h   = (const float*)d_in[0];
    const int*   src = (const int*)d_in[1];
    const int*   dst = (const int*)d_in[2];
    const float* W   = (const float*)d_in[3];
    const float* b   = (const float*)d_in[4];
    float* out = (float*)d_out;

    fill_kernel<<<(NE / 4 + 255) / 256, 256>>>(src, dst);
    fused_kernel<<<(NN + 63) / 64, 256>>>(h, W, b, out);
}